// round 12
// baseline (speedup 1.0000x reference)
#include <cuda_runtime.h>
#include <math.h>

#define NN 100000
#define NE 1250000
#define NG 1024
#define NB 98            // ceil(NN/1024) scan blocks per graph

// ---------------- scratch (device globals; no allocation allowed) ----------------
struct Edge { int s; float w; };
__device__ __align__(16) int   g_degi[2 * NN];        // in-degree (int)
__device__ __align__(16) int   g_cursor[2 * NN];      // CSR fill cursors
__device__ __align__(16) int   g_rowptr[2 * (NN + 1)];
__device__ __align__(16) int   g_bsum[2 * NB];
__device__ __align__(16) int   g_boff[2 * NB];
__device__ __align__(16) float g_dinv[2 * NN];
__device__ __align__(16) Edge  g_edge[2 * NE];        // CSR payload: {src, dinv[s]*dinv[d]}
__device__ __align__(16) float g_tab[300 * 64];       // layer-1 per-type tables (ast:0..199, cfg:200..299)
__device__ __align__(16) float g_x[2 * NN * 64];      // layer-1 output features (both graphs)
__device__ __align__(16) float g_pooled[2 * NG * 64];
__device__ __align__(16) float g_cnt[2 * NG];
__device__ __align__(16) float g_hsem[NG * 64];

__device__ __forceinline__ void red4(float* p, float x, float y, float z, float w) {
    asm volatile("red.global.add.v4.f32 [%0], {%1,%2,%3,%4};"
                 :: "l"(p), "f"(x), "f"(y), "f"(z), "f"(w) : "memory");
}

// Edge is layout-compatible with float2; __ldg only supports builtin types.
__device__ __forceinline__ void ldg_edge(const Edge* p, int& s, float& w) {
    float2 raw = __ldg((const float2*)p);
    s = __float_as_int(raw.x);
    w = raw.y;
}

// ---------------- init: zero counters ----------------
__global__ void init_k() {
    int i = blockIdx.x * blockDim.x + threadIdx.x;
    if (i < 2 * NN) { g_degi[i] = 0; g_cursor[i] = 0; }
    if (i < 2 * NG * 64) g_pooled[i] = 0.f;
    if (i < 2 * NG)      g_cnt[i] = 0.f;
}

// ---------------- int degree, both graphs ----------------
__global__ void degi_both_k(const int* __restrict__ ast_dst, const int* __restrict__ cfg_dst) {
    int idx = blockIdx.x * blockDim.x + threadIdx.x;
    if (idx >= 2 * NE) return;
    int gn = idx / NE, e = idx - gn * NE;
    const int* dst = gn ? cfg_dst : ast_dst;
    atomicAdd(&g_degi[gn * NN + dst[e]], 1);
}

__global__ void dinv_k() {
    int i = blockIdx.x * blockDim.x + threadIdx.x;
    if (i < 2 * NN) g_dinv[i] = rsqrtf((float)g_degi[i] + 1.f);
}

// ---------------- 3-phase exclusive scan of degrees -> rowptr ----------------
__global__ void scanA_k() {       // grid = 2*NB, block = 1024
    __shared__ int sm[1024];
    int gn = blockIdx.x / NB, b = blockIdx.x % NB;
    int i = b * 1024 + threadIdx.x;
    int v = (i < NN) ? g_degi[gn * NN + i] : 0;
    sm[threadIdx.x] = v;
    __syncthreads();
    for (int off = 1; off < 1024; off <<= 1) {
        int t = (threadIdx.x >= off) ? sm[threadIdx.x - off] : 0;
        __syncthreads();
        sm[threadIdx.x] += t;
        __syncthreads();
    }
    if (i < NN) g_rowptr[gn * (NN + 1) + i] = sm[threadIdx.x] - v;   // exclusive (local)
    if (threadIdx.x == 1023) g_bsum[gn * NB + b] = sm[1023];
}

__global__ void scanB_k() {       // grid = 2, block = 128
    __shared__ int sm[128];
    int gn = blockIdx.x;
    int v = (threadIdx.x < NB) ? g_bsum[gn * NB + threadIdx.x] : 0;
    sm[threadIdx.x] = v;
    __syncthreads();
    for (int off = 1; off < 128; off <<= 1) {
        int t = (threadIdx.x >= off) ? sm[threadIdx.x - off] : 0;
        __syncthreads();
        sm[threadIdx.x] += t;
        __syncthreads();
    }
    if (threadIdx.x < NB) g_boff[gn * NB + threadIdx.x] = sm[threadIdx.x] - v;
}

__global__ void scanC_k() {       // add block offsets; set rowptr[NN]=NE
    int idx = blockIdx.x * blockDim.x + threadIdx.x;
    int gn = idx / NN, i = idx % NN;
    if (idx < 2 * NN) g_rowptr[gn * (NN + 1) + i] += g_boff[gn * NB + (i >> 10)];
    if (idx == 0) { g_rowptr[NN] = NE; g_rowptr[NN + 1 + NN] = NE; }
}

// ---------------- CSR fill, both graphs ----------------
__global__ void fill_both_k(const int* __restrict__ ast_src, const int* __restrict__ ast_dst,
                            const int* __restrict__ cfg_src, const int* __restrict__ cfg_dst) {
    int idx = blockIdx.x * blockDim.x + threadIdx.x;
    if (idx >= 2 * NE) return;
    int gn = idx / NE, e = idx - gn * NE;
    const int* src = gn ? cfg_src : ast_src;
    const int* dst = gn ? cfg_dst : ast_dst;
    int s = src[e], d = dst[e];
    float w = g_dinv[gn * NN + s] * g_dinv[gn * NN + d];
    int slot = g_rowptr[gn * (NN + 1) + d] + atomicAdd(&g_cursor[gn * NN + d], 1);
    Edge ed; ed.s = s; ed.w = w;
    g_edge[gn * NE + slot] = ed;
}

// ---------------- per-type tables, both: tab = emb @ W1 ----------------
__global__ void tab_both_k(const float* __restrict__ ast_emb, const float* __restrict__ ast_W1,
                           const float* __restrict__ cfg_emb, const float* __restrict__ cfg_W1) {
    int r = blockIdx.x, f = threadIdx.x;
    const float* emb = (r < 200) ? ast_emb : cfg_emb;
    const float* W   = (r < 200) ? ast_W1  : cfg_W1;
    int rr = (r < 200) ? r : r - 200;
    __shared__ float se[64];
    se[f] = emb[rr * 64 + f];
    __syncthreads();
    float a = 0.f;
#pragma unroll
    for (int k = 0; k < 64; k++) a += se[k] * W[k * 64 + f];
    g_tab[r * 64 + f] = a;
}

// ---------------- layer-1 pull (both graphs): x = relu(sum_e w*tab[type[src]] + self + b1) ----------------
__global__ void pull1_both_k(const int* __restrict__ ast_type, const float* __restrict__ ast_b1,
                             const int* __restrict__ cfg_type, const float* __restrict__ cfg_b1) {
    int idx = blockIdx.x * blockDim.x + threadIdx.x;
    if (idx >= 2 * NN * 16) return;
    int ng = idx >> 4;                 // global node in [0, 2NN)
    int gn = (ng >= NN) ? 1 : 0;
    int n  = ng - gn * NN;
    int f  = (idx & 15) << 2;
    const int*   type = gn ? cfg_type : ast_type;
    const float* b1   = gn ? cfg_b1   : ast_b1;
    int tofs = gn * 200;

    int r0 = __ldg(&g_rowptr[gn * (NN + 1) + n]);
    int r1 = __ldg(&g_rowptr[gn * (NN + 1) + n + 1]);
    float ax = 0.f, ay = 0.f, az = 0.f, aw = 0.f;
    const Edge* ep = g_edge + gn * NE;
    int i = r0;
    for (; i + 1 < r1; i += 2) {       // 2-way unroll on the edge->type->table chain
        int s0, s1; float w0, w1;
        ldg_edge(&ep[i], s0, w0);
        ldg_edge(&ep[i + 1], s1, w1);
        int t0 = __ldg(type + s0);
        int t1 = __ldg(type + s1);
        const float4 v0 = *(const float4*)&g_tab[(tofs + t0) * 64 + f];
        const float4 v1 = *(const float4*)&g_tab[(tofs + t1) * 64 + f];
        ax += w0 * v0.x + w1 * v1.x;
        ay += w0 * v0.y + w1 * v1.y;
        az += w0 * v0.z + w1 * v1.z;
        aw += w0 * v0.w + w1 * v1.w;
    }
    if (i < r1) {
        int s0; float w0;
        ldg_edge(&ep[i], s0, w0);
        int t0 = __ldg(type + s0);
        const float4 v0 = *(const float4*)&g_tab[(tofs + t0) * 64 + f];
        ax += w0 * v0.x; ay += w0 * v0.y; az += w0 * v0.z; aw += w0 * v0.w;
    }
    float di = g_dinv[gn * NN + n];
    float s2 = di * di;
    int tn = __ldg(type + n);
    const float4 h  = *(const float4*)&g_tab[(tofs + tn) * 64 + f];
    const float4 bb = *(const float4*)&b1[f];
    float4 o;
    o.x = fmaxf(ax + h.x * s2 + bb.x, 0.f);
    o.y = fmaxf(ay + h.y * s2 + bb.y, 0.f);
    o.z = fmaxf(az + h.z * s2 + bb.z, 0.f);
    o.w = fmaxf(aw + h.w * s2 + bb.w, 0.f);
    *(float4*)&g_x[ng * 64 + f] = o;
}

// ---------------- layer-2 pull + pool (both graphs) ----------------
__global__ void pull2_both_k(const int* __restrict__ ast_batch, const int* __restrict__ cfg_batch) {
    int idx = blockIdx.x * blockDim.x + threadIdx.x;
    if (idx >= 2 * NN * 16) return;
    int ng = idx >> 4;
    int gn = (ng >= NN) ? 1 : 0;
    int n  = ng - gn * NN;
    int f  = (idx & 15) << 2;
    const int* batch = gn ? cfg_batch : ast_batch;

    int r0 = __ldg(&g_rowptr[gn * (NN + 1) + n]);
    int r1 = __ldg(&g_rowptr[gn * (NN + 1) + n + 1]);
    float ax = 0.f, ay = 0.f, az = 0.f, aw = 0.f;
    const Edge* ep = g_edge + gn * NE;
    const float* xb = g_x + gn * NN * 64;
    int i = r0;
    // 4-way unroll: 4 independent random 16B gathers in flight per thread
    for (; i + 3 < r1; i += 4) {
        int s0, s1, s2i, s3; float w0, w1, w2, w3;
        ldg_edge(&ep[i],     s0,  w0);
        ldg_edge(&ep[i + 1], s1,  w1);
        ldg_edge(&ep[i + 2], s2i, w2);
        ldg_edge(&ep[i + 3], s3,  w3);
        const float4 v0 = *(const float4*)&xb[s0  * 64 + f];
        const float4 v1 = *(const float4*)&xb[s1  * 64 + f];
        const float4 v2 = *(const float4*)&xb[s2i * 64 + f];
        const float4 v3 = *(const float4*)&xb[s3  * 64 + f];
        ax += w0 * v0.x + w1 * v1.x + w2 * v2.x + w3 * v3.x;
        ay += w0 * v0.y + w1 * v1.y + w2 * v2.y + w3 * v3.y;
        az += w0 * v0.z + w1 * v1.z + w2 * v2.z + w3 * v3.z;
        aw += w0 * v0.w + w1 * v1.w + w2 * v2.w + w3 * v3.w;
    }
    for (; i < r1; i++) {
        int s0; float w0;
        ldg_edge(&ep[i], s0, w0);
        const float4 v0 = *(const float4*)&xb[s0 * 64 + f];
        ax += w0 * v0.x; ay += w0 * v0.y; az += w0 * v0.z; aw += w0 * v0.w;
    }
    float di = g_dinv[gn * NN + n];
    float s2 = di * di;
    const float4 x = *(const float4*)&xb[n * 64 + f];
    int b = __ldg(batch + n);
    red4(&g_pooled[(gn * NG + b) * 64 + f],
         ax + x.x * s2, ay + x.y * s2, az + x.z * s2, aw + x.w * s2);
    if ((idx & 15) == 0) atomicAdd(&g_cnt[gn * NG + b], 1.f);
}

// ---------------- semantic GEMM: hsem = relu(S[1024,768] @ Wsem[768,64] + bsem) ----------------
__global__ void sem_k(const float* __restrict__ S, const float* __restrict__ W,
                      const float* __restrict__ bias) {
    __shared__ float sW[64 * 64];
    __shared__ float sS[64 * 64];
    int tid = threadIdx.x;
    int c = tid & 63;
    int r0 = tid >> 6;
    int g0 = blockIdx.x * 64;
    float acc[16];
#pragma unroll
    for (int i = 0; i < 16; i++) acc[i] = 0.f;

    for (int kk = 0; kk < 768; kk += 64) {
        for (int j = tid; j < 4096; j += 256) {
            sW[j] = W[kk * 64 + j];
            sS[j] = S[(g0 + (j >> 6)) * 768 + kk + (j & 63)];
        }
        __syncthreads();
#pragma unroll 8
        for (int k = 0; k < 64; k++) {
            float wv = sW[k * 64 + c];
#pragma unroll
            for (int i = 0; i < 16; i++)
                acc[i] += sS[(r0 + 4 * i) * 64 + k] * wv;
        }
        __syncthreads();
    }
#pragma unroll
    for (int i = 0; i < 16; i++)
        g_hsem[(g0 + r0 + 4 * i) * 64 + c] = fmaxf(acc[i] + bias[c], 0.f);
}

// ---------------- head: per-graph block, fusion + LayerNorm + classifier ----------------
__global__ void head_k(const float* __restrict__ W2a, const float* __restrict__ b2a,
                       const float* __restrict__ W2c, const float* __restrict__ b2c,
                       const float* __restrict__ Wg1, const float* __restrict__ bg1,
                       const float* __restrict__ Wg2, const float* __restrict__ bg2,
                       const float* __restrict__ lng, const float* __restrict__ lnb,
                       const float* __restrict__ Wc,  const float* __restrict__ bc,
                       float* __restrict__ out) {
    int g = blockIdx.x, f = threadIdx.x;
    __shared__ float pa[64], pc[64], ha[64], hc[64], hst[64], hs[64], red[64], hn[64];

    pa[f] = g_pooled[g * 64 + f];
    pc[f] = g_pooled[(NG + g) * 64 + f];
    __syncthreads();

    float ca = g_cnt[g], cc = g_cnt[NG + g];
    float aA = ca * b2a[f], aC = cc * b2c[f];
#pragma unroll 8
    for (int k = 0; k < 64; k++) {
        aA += pa[k] * W2a[k * 64 + f];
        aC += pc[k] * W2c[k * 64 + f];
    }
    ha[f] = aA; hc[f] = aC;
    __syncthreads();

    float z = bg1[f];
#pragma unroll 8
    for (int k = 0; k < 64; k++) z += ha[k] * Wg1[k * 64 + f];
#pragma unroll 8
    for (int k = 0; k < 64; k++) z += hc[k] * Wg1[(64 + k) * 64 + f];
    float gt = 1.f / (1.f + expf(-z));
    float hstruct = gt * aA + (1.f - gt) * aC;
    float hsemv = g_hsem[g * 64 + f];
    hst[f] = hstruct; hs[f] = hsemv;
    __syncthreads();

    float z2 = bg2[f];
#pragma unroll 8
    for (int k = 0; k < 64; k++) z2 += hst[k] * Wg2[k * 64 + f];
#pragma unroll 8
    for (int k = 0; k < 64; k++) z2 += hs[k] * Wg2[(64 + k) * 64 + f];
    float g2 = 1.f / (1.f + expf(-z2));
    float h = g2 * hstruct + (1.f - g2) * hsemv;

    red[f] = h;
    __syncthreads();
    for (int s = 32; s > 0; s >>= 1) { if (f < s) red[f] += red[f + s]; __syncthreads(); }
    float mu = red[0] * (1.f / 64.f);
    __syncthreads();
    float dv = h - mu;
    red[f] = dv * dv;
    __syncthreads();
    for (int s = 32; s > 0; s >>= 1) { if (f < s) red[f] += red[f + s]; __syncthreads(); }
    float var = red[0] * (1.f / 64.f);
    float hnv = dv * rsqrtf(var + 1e-5f) * lng[f] + lnb[f];
    hn[f] = hnv;
    __syncthreads();

    if (f < 2) {
        float o = bc[f];
#pragma unroll 8
        for (int k = 0; k < 64; k++) o += hn[k] * Wc[k * 2 + f];
        out[g * 2 + f] = o;
    }
}

// ---------------- launch ----------------
extern "C" void kernel_launch(void* const* d_in, const int* in_sizes, int n_in,
                              void* d_out, int out_size) {
    const int*   ast_type  = (const int*)d_in[0];
    const int*   ast_src   = (const int*)d_in[1];
    const int*   ast_dst   = ast_src + NE;
    const int*   ast_batch = (const int*)d_in[2];
    const int*   cfg_type  = (const int*)d_in[3];
    const int*   cfg_src   = (const int*)d_in[4];
    const int*   cfg_dst   = cfg_src + NE;
    const int*   cfg_batch = (const int*)d_in[5];
    const float* sem       = (const float*)d_in[6];
    const float* ast_emb   = (const float*)d_in[7];
    const float* cfg_emb   = (const float*)d_in[8];
    const float* ast_W1    = (const float*)d_in[9];
    const float* ast_b1    = (const float*)d_in[10];
    const float* ast_W2    = (const float*)d_in[11];
    const float* ast_b2    = (const float*)d_in[12];
    const float* cfg_W1    = (const float*)d_in[13];
    const float* cfg_b1    = (const float*)d_in[14];
    const float* cfg_W2    = (const float*)d_in[15];
    const float* cfg_b2    = (const float*)d_in[16];
    const float* Wg1       = (const float*)d_in[17];
    const float* bg1       = (const float*)d_in[18];
    const float* Wsem      = (const float*)d_in[19];
    const float* bsem      = (const float*)d_in[20];
    const float* Wg2       = (const float*)d_in[21];
    const float* bg2       = (const float*)d_in[22];
    const float* ln_g      = (const float*)d_in[23];
    const float* ln_b      = (const float*)d_in[24];
    const float* Wc        = (const float*)d_in[25];
    const float* bc        = (const float*)d_in[26];
    float* out = (float*)d_out;

    const int TB = 256;
    const int edge2Blk   = (2 * NE + TB - 1) / TB;
    const int node16x2Blk = (2 * NN * 16 + TB - 1) / TB;
    const int initN     = (2 * NN > 2 * NG * 64) ? 2 * NN : 2 * NG * 64;
    const int initBlk   = (initN + TB - 1) / TB;

    init_k<<<initBlk, TB>>>();

    // CSR build for both graphs (merged launches)
    degi_both_k<<<edge2Blk, TB>>>(ast_dst, cfg_dst);
    dinv_k<<<(2 * NN + TB - 1) / TB, TB>>>();
    scanA_k<<<2 * NB, 1024>>>();
    scanB_k<<<2, 128>>>();
    scanC_k<<<(2 * NN + TB - 1) / TB, TB>>>();
    fill_both_k<<<edge2Blk, TB>>>(ast_src, ast_dst, cfg_src, cfg_dst);

    // per-type layer-1 tables (both graphs, one launch)
    tab_both_k<<<300, 64>>>(ast_emb, ast_W1, cfg_emb, cfg_W1);

    // both graphs in one launch per layer
    pull1_both_k<<<node16x2Blk, TB>>>(ast_type, ast_b1, cfg_type, cfg_b1);
    pull2_both_k<<<node16x2Blk, TB>>>(ast_batch, cfg_batch);

    // semantic branch + fused head
    sem_k<<<NG / 64, TB>>>(sem, Wsem, bsem);
    head_k<<<NG, 64>>>(ast_W2, ast_b2, cfg_W2, cfg_b2,
                       Wg1, bg1, Wg2, bg2, ln_g, ln_b, Wc, bc, out);
}

// round 15
// speedup vs baseline: 1.1276x; 1.1276x over previous
#include <cuda_runtime.h>
#include <cuda_fp16.h>
#include <math.h>

#define NN 100000
#define NE 1250000
#define NG 1024
#define NB 98            // ceil(NN/1024) scan blocks per graph

// ---------------- scratch (device globals; no allocation allowed) ----------------
struct Edge { int s; float w; };
__device__ __align__(16) int    g_degi[2 * NN];        // in-degree (int)
__device__ __align__(16) int    g_cursor[2 * NN];      // CSR fill cursors
__device__ __align__(16) int    g_rowptr[2 * (NN + 1)];
__device__ __align__(16) int    g_bsum[2 * NB];
__device__ __align__(16) int    g_boff[2 * NB];
__device__ __align__(16) float  g_dinv[2 * NN];
__device__ __align__(16) Edge   g_edge[2 * NE];        // CSR payload: {src, dinv[s]*dinv[d]}
__device__ __align__(16) float  g_tab[300 * 64];       // layer-1 per-type tables
__device__ __align__(16) __half g_x[NN * 64];          // layer-1 features in fp16 (halved gather traffic)
__device__ __align__(16) float  g_pooled[2 * NG * 64];
__device__ __align__(16) float  g_cnt[2 * NG];
__device__ __align__(16) float  g_hsem[NG * 64];

__device__ __forceinline__ void red4(float* p, float x, float y, float z, float w) {
    asm volatile("red.global.add.v4.f32 [%0], {%1,%2,%3,%4};"
                 :: "l"(p), "f"(x), "f"(y), "f"(z), "f"(w) : "memory");
}

// Edge is layout-compatible with float2; __ldg only supports builtin types.
__device__ __forceinline__ void ldg_edge(const Edge* p, int& s, float& w) {
    float2 raw = __ldg((const float2*)p);
    s = __float_as_int(raw.x);
    w = raw.y;
}

// Load 4 consecutive half features as 4 floats (8B load).
__device__ __forceinline__ void ldg_h4(const __half* p, float& a, float& b, float& c, float& d) {
    uint2 r = __ldg((const uint2*)p);
    __half2 h0 = *(__half2*)&r.x;
    __half2 h1 = *(__half2*)&r.y;
    float2 f0 = __half22float2(h0);
    float2 f1 = __half22float2(h1);
    a = f0.x; b = f0.y; c = f1.x; d = f1.y;
}

// ---------------- init: zero counters ----------------
__global__ void init_k() {
    int i = blockIdx.x * blockDim.x + threadIdx.x;
    if (i < 2 * NN) { g_degi[i] = 0; g_cursor[i] = 0; }
    if (i < 2 * NG * 64) g_pooled[i] = 0.f;
    if (i < 2 * NG)      g_cnt[i] = 0.f;
}

// ---------------- int degree ----------------
__global__ void degi_k(const int* __restrict__ dst, int gn) {
    int e = blockIdx.x * blockDim.x + threadIdx.x;
    if (e < NE) atomicAdd(&g_degi[gn * NN + dst[e]], 1);
}

__global__ void dinv_k() {
    int i = blockIdx.x * blockDim.x + threadIdx.x;
    if (i < 2 * NN) g_dinv[i] = rsqrtf((float)g_degi[i] + 1.f);
}

// ---------------- 3-phase exclusive scan of degrees -> rowptr ----------------
__global__ void scanA_k() {       // grid = 2*NB, block = 1024
    __shared__ int sm[1024];
    int gn = blockIdx.x / NB, b = blockIdx.x % NB;
    int i = b * 1024 + threadIdx.x;
    int v = (i < NN) ? g_degi[gn * NN + i] : 0;
    sm[threadIdx.x] = v;
    __syncthreads();
    for (int off = 1; off < 1024; off <<= 1) {
        int t = (threadIdx.x >= off) ? sm[threadIdx.x - off] : 0;
        __syncthreads();
        sm[threadIdx.x] += t;
        __syncthreads();
    }
    if (i < NN) g_rowptr[gn * (NN + 1) + i] = sm[threadIdx.x] - v;   // exclusive (local)
    if (threadIdx.x == 1023) g_bsum[gn * NB + b] = sm[1023];
}

__global__ void scanB_k() {       // grid = 2, block = 128
    __shared__ int sm[128];
    int gn = blockIdx.x;
    int v = (threadIdx.x < NB) ? g_bsum[gn * NB + threadIdx.x] : 0;
    sm[threadIdx.x] = v;
    __syncthreads();
    for (int off = 1; off < 128; off <<= 1) {
        int t = (threadIdx.x >= off) ? sm[threadIdx.x - off] : 0;
        __syncthreads();
        sm[threadIdx.x] += t;
        __syncthreads();
    }
    if (threadIdx.x < NB) g_boff[gn * NB + threadIdx.x] = sm[threadIdx.x] - v;
}

__global__ void scanC_k() {       // add block offsets; set rowptr[NN]=NE
    int idx = blockIdx.x * blockDim.x + threadIdx.x;
    int gn = idx / NN, i = idx % NN;
    if (idx < 2 * NN) g_rowptr[gn * (NN + 1) + i] += g_boff[gn * NB + (i >> 10)];
    if (idx == 0) { g_rowptr[NN] = NE; g_rowptr[NN + 1 + NN] = NE; }
}

// ---------------- CSR fill: packed {src, weight} sorted by dst ----------------
__global__ void fill_k(const int* __restrict__ src, const int* __restrict__ dst, int gn) {
    int e = blockIdx.x * blockDim.x + threadIdx.x;
    if (e >= NE) return;
    int s = src[e], d = dst[e];
    float w = g_dinv[gn * NN + s] * g_dinv[gn * NN + d];
    int slot = g_rowptr[gn * (NN + 1) + d] + atomicAdd(&g_cursor[gn * NN + d], 1);
    Edge ed; ed.s = s; ed.w = w;
    g_edge[gn * NE + slot] = ed;
}

// ---------------- per-type table: tab = emb @ W1 ----------------
__global__ void tab_k(const float* __restrict__ emb, const float* __restrict__ W, int tofs) {
    int r = blockIdx.x, f = threadIdx.x;
    __shared__ float se[64];
    se[f] = emb[r * 64 + f];
    __syncthreads();
    float a = 0.f;
#pragma unroll
    for (int k = 0; k < 64; k++) a += se[k] * W[k * 64 + f];
    g_tab[(tofs + r) * 64 + f] = a;
}

// ---------------- layer-1 pull: x = relu(sum_e w*tab[type[src]] + self + b1), stored fp16 ----------------
__global__ void pull1_k(const int* __restrict__ type, const float* __restrict__ b1,
                        int gn, int tofs) {
    int idx = blockIdx.x * blockDim.x + threadIdx.x;
    if (idx >= NN * 16) return;
    int n = idx >> 4, f = (idx & 15) << 2;
    int r0 = __ldg(&g_rowptr[gn * (NN + 1) + n]);
    int r1 = __ldg(&g_rowptr[gn * (NN + 1) + n + 1]);
    float ax = 0.f, ay = 0.f, az = 0.f, aw = 0.f;
    const Edge* ep = g_edge + gn * NE;
    for (int i = r0; i < r1; i++) {
        int s; float w;
        ldg_edge(&ep[i], s, w);
        int t = __ldg(type + s);
        const float4 v = *(const float4*)&g_tab[(tofs + t) * 64 + f];
        ax += w * v.x; ay += w * v.y; az += w * v.z; aw += w * v.w;
    }
    float di = g_dinv[gn * NN + n];
    float s2 = di * di;
    int tn = __ldg(type + n);
    const float4 h  = *(const float4*)&g_tab[(tofs + tn) * 64 + f];
    const float4 bb = *(const float4*)&b1[f];
    float ox = fmaxf(ax + h.x * s2 + bb.x, 0.f);
    float oy = fmaxf(ay + h.y * s2 + bb.y, 0.f);
    float oz = fmaxf(az + h.z * s2 + bb.z, 0.f);
    float ow = fmaxf(aw + h.w * s2 + bb.w, 0.f);
    __half2 h0 = __floats2half2_rn(ox, oy);
    __half2 h1 = __floats2half2_rn(oz, ow);
    uint2 pk;
    pk.x = *(unsigned int*)&h0;
    pk.y = *(unsigned int*)&h1;
    *(uint2*)&g_x[n * 64 + f] = pk;
}

// ---------------- layer-2 pull + pool: pooled[batch] += sum_e w*x[src] + x*dinv^2 ----------------
__global__ void pull2_k(const int* __restrict__ batch, int gn, int pofs) {
    int idx = blockIdx.x * blockDim.x + threadIdx.x;
    if (idx >= NN * 16) return;
    int n = idx >> 4, f = (idx & 15) << 2;
    int r0 = __ldg(&g_rowptr[gn * (NN + 1) + n]);
    int r1 = __ldg(&g_rowptr[gn * (NN + 1) + n + 1]);
    float ax = 0.f, ay = 0.f, az = 0.f, aw = 0.f;
    const Edge* ep = g_edge + gn * NE;
    int i = r0;
    // 2-way unroll for explicit MLP on the random 8B gathers
    for (; i + 1 < r1; i += 2) {
        int s0, s1; float w0, w1;
        ldg_edge(&ep[i], s0, w0);
        ldg_edge(&ep[i + 1], s1, w1);
        float v0x, v0y, v0z, v0w, v1x, v1y, v1z, v1w;
        ldg_h4(&g_x[s0 * 64 + f], v0x, v0y, v0z, v0w);
        ldg_h4(&g_x[s1 * 64 + f], v1x, v1y, v1z, v1w);
        ax += w0 * v0x + w1 * v1x;
        ay += w0 * v0y + w1 * v1y;
        az += w0 * v0z + w1 * v1z;
        aw += w0 * v0w + w1 * v1w;
    }
    if (i < r1) {
        int s0; float w0;
        ldg_edge(&ep[i], s0, w0);
        float v0x, v0y, v0z, v0w;
        ldg_h4(&g_x[s0 * 64 + f], v0x, v0y, v0z, v0w);
        ax += w0 * v0x; ay += w0 * v0y; az += w0 * v0z; aw += w0 * v0w;
    }
    float di = g_dinv[gn * NN + n];
    float s2 = di * di;
    float xx, xy, xz, xw;
    ldg_h4(&g_x[n * 64 + f], xx, xy, xz, xw);
    int b = __ldg(batch + n);
    red4(&g_pooled[(pofs + b) * 64 + f],
         ax + xx * s2, ay + xy * s2, az + xz * s2, aw + xw * s2);
    if ((idx & 15) == 0) atomicAdd(&g_cnt[pofs + b], 1.f);
}

// ---------------- semantic GEMM: hsem = relu(S[1024,768] @ Wsem[768,64] + bsem) ----------------
__global__ void sem_k(const float* __restrict__ S, const float* __restrict__ W,
                      const float* __restrict__ bias) {
    __shared__ float sW[64 * 64];
    __shared__ float sS[64 * 64];
    int tid = threadIdx.x;
    int c = tid & 63;
    int r0 = tid >> 6;
    int g0 = blockIdx.x * 64;
    float acc[16];
#pragma unroll
    for (int i = 0; i < 16; i++) acc[i] = 0.f;

    for (int kk = 0; kk < 768; kk += 64) {
        for (int j = tid; j < 4096; j += 256) {
            sW[j] = W[kk * 64 + j];
            sS[j] = S[(g0 + (j >> 6)) * 768 + kk + (j & 63)];
        }
        __syncthreads();
#pragma unroll 8
        for (int k = 0; k < 64; k++) {
            float wv = sW[k * 64 + c];
#pragma unroll
            for (int i = 0; i < 16; i++)
                acc[i] += sS[(r0 + 4 * i) * 64 + k] * wv;
        }
        __syncthreads();
    }
#pragma unroll
    for (int i = 0; i < 16; i++)
        g_hsem[(g0 + r0 + 4 * i) * 64 + c] = fmaxf(acc[i] + bias[c], 0.f);
}

// ---------------- head: per-graph block, fusion + LayerNorm + classifier ----------------
__global__ void head_k(const float* __restrict__ W2a, const float* __restrict__ b2a,
                       const float* __restrict__ W2c, const float* __restrict__ b2c,
                       const float* __restrict__ Wg1, const float* __restrict__ bg1,
                       const float* __restrict__ Wg2, const float* __restrict__ bg2,
                       const float* __restrict__ lng, const float* __restrict__ lnb,
                       const float* __restrict__ Wc,  const float* __restrict__ bc,
                       float* __restrict__ out) {
    int g = blockIdx.x, f = threadIdx.x;
    __shared__ float pa[64], pc[64], ha[64], hc[64], hst[64], hs[64], red[64], hn[64];

    pa[f] = g_pooled[g * 64 + f];
    pc[f] = g_pooled[(NG + g) * 64 + f];
    __syncthreads();

    float ca = g_cnt[g], cc = g_cnt[NG + g];
    float aA = ca * b2a[f], aC = cc * b2c[f];
#pragma unroll 8
    for (int k = 0; k < 64; k++) {
        aA += pa[k] * W2a[k * 64 + f];
        aC += pc[k] * W2c[k * 64 + f];
    }
    ha[f] = aA; hc[f] = aC;
    __syncthreads();

    float z = bg1[f];
#pragma unroll 8
    for (int k = 0; k < 64; k++) z += ha[k] * Wg1[k * 64 + f];
#pragma unroll 8
    for (int k = 0; k < 64; k++) z += hc[k] * Wg1[(64 + k) * 64 + f];
    float gt = 1.f / (1.f + expf(-z));
    float hstruct = gt * aA + (1.f - gt) * aC;
    float hsemv = g_hsem[g * 64 + f];
    hst[f] = hstruct; hs[f] = hsemv;
    __syncthreads();

    float z2 = bg2[f];
#pragma unroll 8
    for (int k = 0; k < 64; k++) z2 += hst[k] * Wg2[k * 64 + f];
#pragma unroll 8
    for (int k = 0; k < 64; k++) z2 += hs[k] * Wg2[(64 + k) * 64 + f];
    float g2 = 1.f / (1.f + expf(-z2));
    float h = g2 * hstruct + (1.f - g2) * hsemv;

    red[f] = h;
    __syncthreads();
    for (int s = 32; s > 0; s >>= 1) { if (f < s) red[f] += red[f + s]; __syncthreads(); }
    float mu = red[0] * (1.f / 64.f);
    __syncthreads();
    float dv = h - mu;
    red[f] = dv * dv;
    __syncthreads();
    for (int s = 32; s > 0; s >>= 1) { if (f < s) red[f] += red[f + s]; __syncthreads(); }
    float var = red[0] * (1.f / 64.f);
    float hnv = dv * rsqrtf(var + 1e-5f) * lng[f] + lnb[f];
    hn[f] = hnv;
    __syncthreads();

    if (f < 2) {
        float o = bc[f];
#pragma unroll 8
        for (int k = 0; k < 64; k++) o += hn[k] * Wc[k * 2 + f];
        out[g * 2 + f] = o;
    }
}

// ---------------- launch ----------------
extern "C" void kernel_launch(void* const* d_in, const int* in_sizes, int n_in,
                              void* d_out, int out_size) {
    const int*   ast_type  = (const int*)d_in[0];
    const int*   ast_src   = (const int*)d_in[1];
    const int*   ast_dst   = ast_src + NE;
    const int*   ast_batch = (const int*)d_in[2];
    const int*   cfg_type  = (const int*)d_in[3];
    const int*   cfg_src   = (const int*)d_in[4];
    const int*   cfg_dst   = cfg_src + NE;
    const int*   cfg_batch = (const int*)d_in[5];
    const float* sem       = (const float*)d_in[6];
    const float* ast_emb   = (const float*)d_in[7];
    const float* cfg_emb   = (const float*)d_in[8];
    const float* ast_W1    = (const float*)d_in[9];
    const float* ast_b1    = (const float*)d_in[10];
    const float* ast_W2    = (const float*)d_in[11];
    const float* ast_b2    = (const float*)d_in[12];
    const float* cfg_W1    = (const float*)d_in[13];
    const float* cfg_b1    = (const float*)d_in[14];
    const float* cfg_W2    = (const float*)d_in[15];
    const float* cfg_b2    = (const float*)d_in[16];
    const float* Wg1       = (const float*)d_in[17];
    const float* bg1       = (const float*)d_in[18];
    const float* Wsem      = (const float*)d_in[19];
    const float* bsem      = (const float*)d_in[20];
    const float* Wg2       = (const float*)d_in[21];
    const float* bg2       = (const float*)d_in[22];
    const float* ln_g      = (const float*)d_in[23];
    const float* ln_b      = (const float*)d_in[24];
    const float* Wc        = (const float*)d_in[25];
    const float* bc        = (const float*)d_in[26];
    float* out = (float*)d_out;

    const int TB = 256;
    const int edgeBlk   = (NE + TB - 1) / TB;
    const int node16Blk = (NN * 16 + TB - 1) / TB;
    const int initN     = (2 * NN > 2 * NG * 64) ? 2 * NN : 2 * NG * 64;
    const int initBlk   = (initN + TB - 1) / TB;

    init_k<<<initBlk, TB>>>();

    // CSR build for both graphs
    degi_k<<<edgeBlk, TB>>>(ast_dst, 0);
    degi_k<<<edgeBlk, TB>>>(cfg_dst, 1);
    dinv_k<<<(2 * NN + TB - 1) / TB, TB>>>();
    scanA_k<<<2 * NB, 1024>>>();
    scanB_k<<<2, 128>>>();
    scanC_k<<<(2 * NN + TB - 1) / TB, TB>>>();
    fill_k<<<edgeBlk, TB>>>(ast_src, ast_dst, 0);
    fill_k<<<edgeBlk, TB>>>(cfg_src, cfg_dst, 1);

    // per-type layer-1 tables
    tab_k<<<200, 64>>>(ast_emb, ast_W1, 0);
    tab_k<<<100, 64>>>(cfg_emb, cfg_W1, 200);

    // AST graph (g_x reused, so graphs run sequentially)
    pull1_k<<<node16Blk, TB>>>(ast_type, ast_b1, 0, 0);
    pull2_k<<<node16Blk, TB>>>(ast_batch, 0, 0);

    // CFG graph
    pull1_k<<<node16Blk, TB>>>(cfg_type, cfg_b1, 1, 200);
    pull2_k<<<node16Blk, TB>>>(cfg_batch, 1, NG);

    // semantic branch + fused head
    sem_k<<<NG / 64, TB>>>(sem, Wsem, bsem);
    head_k<<<NG, 64>>>(ast_W2, ast_b2, cfg_W2, cfg_b2,
                       Wg1, bg1, Wg2, bg2, ln_g, ln_b, Wc, bc, out);
}